// round 16
// baseline (speedup 1.0000x reference)
#include <cuda_runtime.h>
#include <cuda_fp16.h>
#include <math.h>
#include <stdint.h>

// Problem constants
constexpr int Bk   = 16;
constexpr int HWk  = 4096;
constexpr int Qk   = 100;
constexpr int Ck   = 256;
constexpr int Hk   = 8;
constexpr int Dk   = 32;
constexpr int HIDk = 2048;
constexpr int CHk  = 8;
constexpr float SCALEk = 0.17677669529663687f;  // 32^-0.5

// Scratch (device globals: allocation-free rule)
__device__ float  g_pacc[CHk * Bk * Hk * Qk * Dk];
__device__ float  g_ps[CHk * Bk * Hk * Qk];
__device__ float  g_bias4[4 * Ck];
// fp16 pipeline buffers
__device__ __half g_vis_h[Bk * HWk * Ck];
__device__ __half g_lang_h[Bk * Qk * Ck];
__device__ __half g_kv_h[2 * Bk * HWk * Ck];   // [0]=vk, [1]=vv
__device__ __half g_lkv_h[2 * Bk * Qk * Ck];   // [0]=lk, [1]=lv
__device__ __half g_va_h[Bk * Qk * Ck];
__device__ __half g_la_h[Bk * HWk * Ck];
__device__ __half g_fm_h[Bk * Qk * HWk];
__device__ __half g_hid_h[Bk * Qk * HIDk];
__device__ __half g_wT_h[4 * Ck * Ck];
__device__ __half g_w0T_h[HIDk * HWk];
__device__ __half g_w1T_h[Ck * HIDk];

// ---------------------------------------------------------------------------
// PTX helpers (plain-sm_100-legal)
// ---------------------------------------------------------------------------
__device__ __forceinline__ uint32_t smem_u32(const void* p) {
    uint32_t a;
    asm("{ .reg .u64 t; cvta.to.shared.u64 t, %1; cvt.u32.u64 %0, t; }"
        : "=r"(a) : "l"(p));
    return a;
}
__device__ __forceinline__ void cpa16(uint32_t dst, const void* src, int srcsz) {
    asm volatile("cp.async.cg.shared.global [%0], [%1], 16, %2;"
                 :: "r"(dst), "l"(src), "r"(srcsz));
}
__device__ __forceinline__ void cpa_commit() {
    asm volatile("cp.async.commit_group;" ::: "memory");
}
__device__ __forceinline__ void cpa_wait1() {
    asm volatile("cp.async.wait_group 1;" ::: "memory");
}
__device__ __forceinline__ void cpa_wait0() {
    asm volatile("cp.async.wait_group 0;" ::: "memory");
}
__device__ __forceinline__ void ldsm4(uint32_t* r, uint32_t a) {
    asm volatile("ldmatrix.sync.aligned.m8n8.x4.shared.b16 {%0,%1,%2,%3}, [%4];"
                 : "=r"(r[0]), "=r"(r[1]), "=r"(r[2]), "=r"(r[3]) : "r"(a));
}
__device__ __forceinline__ void ldsm4t(uint32_t* r, uint32_t a) {
    asm volatile("ldmatrix.sync.aligned.m8n8.x4.trans.shared.b16 {%0,%1,%2,%3}, [%4];"
                 : "=r"(r[0]), "=r"(r[1]), "=r"(r[2]), "=r"(r[3]) : "r"(a));
}
__device__ __forceinline__ void mma16816(float* c, const uint32_t* a, const uint32_t* b) {
    asm volatile(
        "mma.sync.aligned.m16n8k16.row.col.f32.f16.f16.f32 "
        "{%0,%1,%2,%3},{%4,%5,%6,%7},{%8,%9},{%0,%1,%2,%3};"
        : "+f"(c[0]), "+f"(c[1]), "+f"(c[2]), "+f"(c[3])
        : "r"(a[0]), "r"(a[1]), "r"(a[2]), "r"(a[3]), "r"(b[0]), "r"(b[1]));
}

// ---------------------------------------------------------------------------
// Fused pre-pass (unchanged)
// ---------------------------------------------------------------------------
constexpr int NB_VIS  = Bk * HWk * Ck / 4 / 256;
constexpr int NB_LANG = Bk * Qk * Ck / 4 / 256;
constexpr int NB_T4   = (Ck / 32) * (Ck / 32) * 4;
constexpr int NB_W0   = (HIDk / 32) * (HWk / 32);
constexpr int NB_W1   = (Ck / 32) * (HIDk / 32);
constexpr int NB_BIAS = 1;
constexpr int NB_PRE  = NB_VIS + NB_LANG + NB_T4 + NB_W0 + NB_W1 + NB_BIAS;

__device__ __forceinline__ void tbody(const float* __restrict__ in,
                                      __half* __restrict__ out,
                                      int R, int C, int bx, int by,
                                      int tx, int ty)
{
    __shared__ float t[32][33];
    int r0 = by * 32, c0 = bx * 32;
#pragma unroll
    for (int i = 0; i < 4; i++)
        t[ty + 8 * i][tx] = in[(size_t)(r0 + ty + 8 * i) * C + c0 + tx];
    __syncthreads();
#pragma unroll
    for (int i = 0; i < 4; i++)
        out[(size_t)(c0 + ty + 8 * i) * R + r0 + tx] =
            __float2half_rn(t[tx][ty + 8 * i]);
}

__global__ __launch_bounds__(256) void prepass(
    const float* __restrict__ vis, const float* __restrict__ lang,
    const float* __restrict__ Wvk, const float* __restrict__ Wvv,
    const float* __restrict__ Wlk, const float* __restrict__ Wlv,
    const float* __restrict__ W0, const float* __restrict__ W1,
    const float* __restrict__ bvk, const float* __restrict__ bvv,
    const float* __restrict__ blk, const float* __restrict__ blv)
{
    int bid = blockIdx.x;
    int tid = threadIdx.x;
    int tx = tid & 31, ty = tid >> 5;

    if (bid < NB_VIS) {
        int i = (bid * 256 + tid) * 4;
        float4 v = *(const float4*)(vis + i);
        *(__half2*)(g_vis_h + i)     = __floats2half2_rn(v.x, v.y);
        *(__half2*)(g_vis_h + i + 2) = __floats2half2_rn(v.z, v.w);
        return;
    }
    bid -= NB_VIS;
    if (bid < NB_LANG) {
        int i = (bid * 256 + tid) * 4;
        float4 v = *(const float4*)(lang + i);
        *(__half2*)(g_lang_h + i)     = __floats2half2_rn(v.x, v.y);
        *(__half2*)(g_lang_h + i + 2) = __floats2half2_rn(v.z, v.w);
        return;
    }
    bid -= NB_LANG;
    if (bid < NB_T4) {
        int z = bid / 64, rem = bid % 64;
        const float* in = (z == 0) ? Wvk : (z == 1) ? Wvv : (z == 2) ? Wlk : Wlv;
        tbody(in, g_wT_h + (size_t)z * Ck * Ck, Ck, Ck, rem % 8, rem / 8, tx, ty);
        return;
    }
    bid -= NB_T4;
    if (bid < NB_W0) {
        tbody(W0, g_w0T_h, HWk, HIDk, bid % (HIDk / 32), bid / (HIDk / 32), tx, ty);
        return;
    }
    bid -= NB_W0;
    if (bid < NB_W1) {
        tbody(W1, g_w1T_h, HIDk, Ck, bid % (Ck / 32), bid / (Ck / 32), tx, ty);
        return;
    }
    {
        int i = tid * 4;
        int j = i >> 8;
        const float* src = (j == 0) ? bvk : (j == 1) ? bvv : (j == 2) ? blk : blv;
        *(float4*)(g_bias4 + i) = *(const float4*)(src + (i & 255));
    }
}

// ---------------------------------------------------------------------------
// fp16 tensor-core GEMM, BM=64, register fragment double-buffering.
//   C[z] = alpha * A[z][M,K] @ B[z][N,K]^T (+bias[z], relu)
// ---------------------------------------------------------------------------
constexpr int STAGES = 3;
constexpr int GEMM_BM = 64;
constexpr int MMH_SMEM = STAGES * (GEMM_BM * 128 + 16384);   // 73728

template <bool RELU, bool HASBIAS, bool OUT32, bool OUTH>
__global__ __launch_bounds__(256, 2) void mm_h(
    const __half* __restrict__ Ag, const __half* __restrict__ Bg,
    const float* __restrict__ bias, float* __restrict__ Cf, __half* __restrict__ Ch,
    int M, int N, int K, float alpha, long sA, long sB, long sC, long sBias)
{
    constexpr int BM = GEMM_BM;
    constexpr int MI = BM / 32;               // 2
    constexpr int ASTG = BM * 128;
    constexpr int STRIDE = ASTG + 16384;

    extern __shared__ char smh[];
    const __half* A = Ag + (size_t)blockIdx.z * sA;
    const __half* B = Bg + (size_t)blockIdx.z * sB;
    const float* bi = HASBIAS ? bias + (size_t)blockIdx.z * sBias : nullptr;

    const int tid = threadIdx.x, lane = tid & 31, warp = tid >> 5;
    const int warp_m = warp >> 2, warp_n = warp & 3;
    const int bm = blockIdx.y * BM, bn = blockIdx.x * 128;
    const uint32_t sbase = smem_u32(smh);
    const int NS = K / 64;

    auto issue = [&](int s) {
        uint32_t ab = sbase + (s % STAGES) * STRIDE;
        uint32_t bb = ab + ASTG;
        int k0 = s * 64;
#pragma unroll
        for (int i = 0; i < BM / 32; i++) {
            int id = tid + 256 * i;
            int r = id >> 3, c = id & 7;
            uint32_t off = r * 128 + ((c ^ (r & 7)) << 4);
            cpa16(ab + off, A + (size_t)(bm + r) * K + k0 + c * 8,
                  (bm + r) < M ? 16 : 0);
        }
#pragma unroll
        for (int i = 0; i < 4; i++) {
            int id = tid + 256 * i;
            int r = id >> 3, c = id & 7;
            uint32_t off = r * 128 + ((c ^ (r & 7)) << 4);
            cpa16(bb + off, B + (size_t)(bn + r) * K + k0 + c * 8, 16);
        }
    };

    float acc[MI][4][4] = {};

    issue(0); cpa_commit();
    if (NS > 1) issue(1);
    cpa_commit();

    for (int s = 0; s < NS; s++) {
        cpa_wait1();
        __syncthreads();
        uint32_t ab = sbase + (s % STAGES) * STRIDE;
        uint32_t bb = ab + ASTG;

        uint32_t af[2][MI][4], bf[2][4][2];
        auto ldA = [&](int ks, uint32_t (*A_)[4]) {
#pragma unroll
            for (int mi = 0; mi < MI; mi++) {
                int row = warp_m * (BM / 2) + mi * 16 + (lane & 15);
                int kc = ks * 2 + ((lane >> 4) & 1);
                ldsm4(A_[mi], ab + row * 128 + ((kc ^ (row & 7)) << 4));
            }
        };
        auto ldB = [&](int ks, uint32_t (*B_)[2]) {
#pragma unroll
            for (int bj = 0; bj < 2; bj++) {
                int row = warp_n * 32 + bj * 16 + (lane & 7) + ((lane >> 4) << 3);
                int kc = ks * 2 + ((lane >> 3) & 1);
                uint32_t t[4];
                ldsm4(t, bb + row * 128 + ((kc ^ (row & 7)) << 4));
                B_[bj * 2][0] = t[0]; B_[bj * 2][1] = t[1];
                B_[bj * 2 + 1][0] = t[2]; B_[bj * 2 + 1][1] = t[3];
            }
        };

        ldA(0, af[0]); ldB(0, bf[0]);
#pragma unroll
        for (int ks = 0; ks < 4; ks++) {
            if (ks < 3) { ldA(ks + 1, af[(ks + 1) & 1]); ldB(ks + 1, bf[(ks + 1) & 1]); }
#pragma unroll
            for (int mi = 0; mi < MI; mi++)
#pragma unroll
                for (int ni = 0; ni < 4; ni++)
                    mma16816(acc[mi][ni], af[ks & 1][mi], bf[ks & 1][ni]);
        }
        if (s + STAGES - 1 < NS) issue(s + STAGES - 1);
        cpa_commit();
    }

    const int rr = lane >> 2, cc2 = (lane & 3) * 2;
#pragma unroll
    for (int mi = 0; mi < MI; mi++) {
        int row0 = bm + warp_m * (BM / 2) + mi * 16 + rr;
#pragma unroll
        for (int ni = 0; ni < 4; ni++) {
            int col = bn + warp_n * 32 + ni * 8 + cc2;
            float b0 = HASBIAS ? bi[col] : 0.f;
            float b1 = HASBIAS ? bi[col + 1] : 0.f;
            float v0 = alpha * acc[mi][ni][0] + b0;
            float v1 = alpha * acc[mi][ni][1] + b1;
            float v2 = alpha * acc[mi][ni][2] + b0;
            float v3 = alpha * acc[mi][ni][3] + b1;
            if (RELU) {
                v0 = fmaxf(v0, 0.f); v1 = fmaxf(v1, 0.f);
                v2 = fmaxf(v2, 0.f); v3 = fmaxf(v3, 0.f);
            }
            if (row0 < M) {
                size_t o = (size_t)blockIdx.z * sC + (size_t)row0 * N + col;
                if (OUT32) *(float2*)(Cf + o) = make_float2(v0, v1);
                if (OUTH)  *(__half2*)(Ch + o) = __floats2half2_rn(v0, v1);
            }
            if (row0 + 8 < M) {
                size_t o = (size_t)blockIdx.z * sC + (size_t)(row0 + 8) * N + col;
                if (OUT32) *(float2*)(Cf + o) = make_float2(v2, v3);
                if (OUTH)  *(__half2*)(Ch + o) = __floats2half2_rn(v2, v3);
            }
        }
    }
}

// ---------------------------------------------------------------------------
// Max-free tensor-core attention (unchanged from R15, 2 CTAs/SM)
// ---------------------------------------------------------------------------
constexpr int OFF_LK  = 0;
constexpr int OFF_VK0 = OFF_LK + 112 * 128;
constexpr int OFF_LVT = OFF_VK0 + 32768;
constexpr int OFF_VVT = OFF_LVT + 48 * 256;
constexpr int OFF_PQ  = OFF_VVT + 48 * 256;
constexpr int OFF_ACC = OFF_PQ + 112 * 256;
constexpr int OFF_SS  = OFF_ACC + 112 * 32 * 4;
constexpr int ATTN_SMEM = OFF_SS + 448;

__global__ __launch_bounds__(256, 2) void attn_tc()
{
    int bh = blockIdx.x, ch = blockIdx.y;
    int b = bh / Hk, h = bh % Hk;
    int tid = threadIdx.x, lane = tid & 31, warp = tid >> 5;
    const int rrL = lane >> 2, tig = lane & 3, ccL = tig * 2;

    const __half* vkg = g_kv_h;
    const __half* vvg = g_kv_h + (size_t)Bk * HWk * Ck;
    const __half* lkg = g_lkv_h;
    const __half* lvg = g_lkv_h + (size_t)Bk * Qk * Ck;

    extern __shared__ char smn[];
    const uint32_t sU = smem_u32(smn);
    float* acc_s = (float*)(smn + OFF_ACC);
    float* s_sv  = (float*)(smn + OFF_SS);

    const int TILES = HWk / 128 / CHk;
    const int t0 = ch * TILES;

    auto issue_vk = [&](int kt, int buf) {
#pragma unroll
        for (int i = 0; i < 2; i++) {
            int id = tid + 256 * i;
            int r = id >> 2, kc = id & 3;
            cpa16(sU + OFF_VK0 + buf * 16384 + r * 128 + ((kc ^ (r & 7)) << 4),
                  vkg + ((size_t)b * HWk + kt * 128 + r) * Ck + h * Dk + kc * 8, 16);
        }
    };
    auto ldg_vv = [&](int kt, uint4* regs) {
#pragma unroll
        for (int i = 0; i < 2; i++) {
            int id = tid + 256 * i;
            int r = id >> 2, kc = id & 3;
            regs[i] = *(const uint4*)(vvg + ((size_t)b * HWk + kt * 128 + r) * Ck
                                      + h * Dk + kc * 8);
        }
    };

    issue_vk(t0, 0); cpa_commit();
    uint4 vvr[2];
    ldg_vv(t0, vvr);

    // ---- one-time setup ----
    for (int i = tid; i < 112 * 4; i += 256) {
        int r = i >> 2, kc = i & 3;
        uint4 v = make_uint4(0, 0, 0, 0);
        if (r < Qk)
            v = *(const uint4*)(lkg + ((size_t)b * Qk + r) * Ck + h * Dk + kc * 8);
        *(uint4*)(smn + OFF_LK + r * 128 + ((kc ^ (r & 7)) << 4)) = v;
    }
    for (int i = tid; i < 32 * 112; i += 256) {
        int q = i >> 5, d = i & 31;
        __half v = __ushort_as_half(0);
        if (q < Qk) v = lvg[((size_t)b * Qk + q) * Ck + h * Dk + d];
        *(__half*)(smn + OFF_LVT + d * 256 + (((q >> 3) ^ (d & 7)) << 4) + (q & 7) * 2) = v;
    }
    for (int i = tid; i < 16 * 128; i += 256) {
        int d = 32 + (i >> 7), c = i & 127;
        __half onesL = (d == 32 && c < Qk) ? __float2half_rn(1.f) : __ushort_as_half(0);
        __half onesV = (d == 32) ? __float2half_rn(1.f) : __ushort_as_half(0);
        uint32_t sw = (((c >> 3) ^ (d & 7)) << 4) + (c & 7) * 2;
        *(__half*)(smn + OFF_LVT + d * 256 + sw) = onesL;
        *(__half*)(smn + OFF_VVT + d * 256 + sw) = onesV;
    }
    for (int i = tid; i < 112 * 32; i += 256) acc_s[i] = 0.f;
    for (int i = tid; i < 112; i += 256) s_sv[i] = 0.f;

    for (int it = 0; it < TILES; it++) {
        const int kt = t0 + it;
        const int k0 = kt * 128;
        const int vb = it & 1;

#pragma unroll
        for (int i = 0; i < 2; i++) {
            int id = tid + 256 * i;
            int r = id >> 2, kc = id & 3;
            uint32_t w[4] = { vvr[i].x, vvr[i].y, vvr[i].z, vvr[i].w };
#pragma unroll
            for (int j = 0; j < 4; j++) {
                __half2 h2 = *reinterpret_cast<__half2*>(&w[j]);
                int d0 = kc * 8 + j * 2, d1 = d0 + 1;
                *(__half*)(smn + OFF_VVT + d0 * 256 +
                           (((r >> 3) ^ (d0 & 7)) << 4) + (r & 7) * 2) = h2.x;
                *(__half*)(smn + OFF_VVT + d1 * 256 +
                           (((r >> 3) ^ (d1 & 7)) << 4) + (r & 7) * 2) = h2.y;
            }
        }

        if (it + 1 < TILES) { issue_vk(kt + 1, vb ^ 1); cpa_commit(); cpa_wait1(); }
        else cpa_wait0();
        __syncthreads();                                  // sync #1

        // ---- S = lk @ vk^T in two mi-halves; exp in registers -> Pq ----
        {
            int n0 = warp * 16;
#pragma unroll
            for (int hf = 0; hf < 2; hf++) {
                const int mBase = hf * 4;
                const int mCnt = hf ? 3 : 4;
                float c[4][2][4] = {};
#pragma unroll
                for (int ks = 0; ks < 2; ks++) {
                    uint32_t bfr[4];
                    {
                        int row = n0 + (lane & 7) + ((lane >> 4) << 3);
                        int kc = ks * 2 + ((lane >> 3) & 1);
                        ldsm4(bfr, sU + OFF_VK0 + vb * 16384 + row * 128 +
                                   ((kc ^ (row & 7)) << 4));
                    }
#pragma unroll
                    for (int mi = 0; mi < 4; mi++) {
                        if (mi >= mCnt) break;
                        uint32_t af[4];
                        int row = (mBase + mi) * 16 + (lane & 15);
                        int kc = ks * 2 + (lane >> 4);
                        ldsm4(af, sU + OFF_LK + row * 128 + ((kc ^ (row & 7)) << 4));
                        uint32_t b0[2] = {bfr[0], bfr[1]}, b1[2] = {bfr[2], bfr[3]};
                        mma16816(c[mi][0], af, b0);
                        mma16816(c[mi][1], af, b1);
                    }
                }
#pragma unroll
                for (int mi = 0; mi < 4; mi++) {
                    if (mi >= mCnt) break;
                    int q0 = (mBase + mi) * 16 + rrL;
#pragma unroll
                    for (int ni = 0; ni < 2; ni++) {
                        int kc0 = n0 + ni * 8 + ccL;
                        float e0 = __expf(c[mi][ni][0] * SCALEk);
                        float e1 = __expf(c[mi][ni][1] * SCALEk);
                        float e2 = __expf(c[mi][ni][2] * SCALEk);
                        float e3 = __expf(c[mi][ni][3] * SCALEk);
                        *(__half2*)(smn + OFF_PQ + q0 * 256 +
                                    (((kc0 >> 3) ^ (q0 & 7)) << 4) + (kc0 & 7) * 2) =
                            __floats2half2_rn(e0, e1);
                        *(__half2*)(smn + OFF_PQ + (q0 + 8) * 256 +
                                    (((kc0 >> 3) ^ ((q0 + 8) & 7)) << 4) + (kc0 & 7) * 2) =
                            __floats2half2_rn(e2, e3);
                    }
                }
            }
        }
        if (it + 1 < TILES) ldg_vv(kt + 1, vvr);
        __syncthreads();                                  // sync #2

        // ---- concurrent: warps 0-3 la MMA (trans A from Pq), warps 4-7 pv MMA ----
        if (warp < 4) {
#pragma unroll
            for (int c2 = 0; c2 < 2; c2++) {
                int m0 = warp * 16 + c2 * 64;
                float c[5][4] = {};
#pragma unroll
                for (int ks = 0; ks < 7; ks++) {
                    uint32_t af[4];
                    {
                        int q = ks * 16 + ((lane >> 4) << 3) + (lane & 7);
                        int mcol = m0 + (((lane >> 3) & 1) << 3);
                        ldsm4t(af, sU + OFF_PQ + q * 256 +
                                   ((((mcol >> 3) ^ (q & 7)) << 4)));
                    }
#pragma unroll
                    for (int bj = 0; bj < 3; bj++) {
                        int row = bj * 16 + (lane & 7) + ((lane >> 4) << 3);
                        int kc = ks * 2 + ((lane >> 3) & 1);
                        uint32_t t[4];
                        ldsm4(t, sU + OFF_LVT + row * 256 + ((kc ^ (row & 7)) << 4));
                        uint32_t b0[2] = {t[0], t[1]}, b1[2] = {t[2], t[3]};
                        mma16816(c[bj * 2], af, b0);
                        if (bj < 2) mma16816(c[bj * 2 + 1], af, b1);
                    }
                }
                int kr0 = m0 + rrL, kr1 = kr0 + 8;
                float cs0 = __shfl_sync(0xFFFFFFFFu, c[4][0], (lane >> 2) << 2);
                float cs1 = __shfl_sync(0xFFFFFFFFu, c[4][2], (lane >> 2) << 2);
                float inv0 = 1.f / cs0, inv1 = 1.f / cs1;
#pragma unroll
                for (int ni = 0; ni < 4; ni++) {
                    int d0 = ni * 8 + ccL;
                    size_t o0 = ((size_t)b * HWk + k0 + kr0) * Ck + h * Dk + d0;
                    size_t o1 = ((size_t)b * HWk + k0 + kr1) * Ck + h * Dk + d0;
                    *(__half2*)(g_la_h + o0) =
                        __floats2half2_rn(c[ni][0] * inv0, c[ni][1] * inv0);
                    *(__half2*)(g_la_h + o1) =
                        __floats2half2_rn(c[ni][2] * inv1, c[ni][3] * inv1);
                }
            }
        } else {
            int wq = warp - 4;
#pragma unroll
            for (int c2 = 0; c2 < 2; c2++) {
                int chunk = wq + c2 * 4;
                if (chunk >= 7) break;
                int m0 = chunk * 16;
                float c[5][4] = {};
#pragma unroll
                for (int ks = 0; ks < 8; ks++) {
                    uint32_t af[4];
                    {
                        int row = m0 + (lane & 15);
                        int kc = ks * 2 + (lane >> 4);
                        ldsm4(af, sU + OFF_PQ + row * 256 + ((kc ^ (row & 7)) << 4));
                    }
#pragma unroll
                    for (int bj = 0; bj < 3; bj++) {
                        int row = bj * 16 + (lane & 7) + ((lane >> 4) << 3);
                        int kc = ks * 2 + ((lane >> 3) & 1);
                        uint32_t t[4];
                        ldsm4(t, sU + OFF_VVT + row * 256 + ((kc ^ (row & 7)) << 4));
                        uint32_t b0[2] = {t[0], t[1]}, b1[2] = {t[2], t[3]};
                        mma16816(c[bj * 2], af, b0);
                        if (bj < 2) mma16816(c[bj * 2 + 1], af, b1);
                    }
                }
                int r0 = m0 + rrL, r1 = r0 + 8;
#pragma unroll
                for (int ni = 0; ni < 4; ni++) {
                    int col = ni * 8 + ccL;
                    acc_s[r0 * 32 + col]     += c[ni][0];
                    acc_s[r0 * 32 + col + 1] += c[ni][1];
                    acc_s[r1 * 32 + col]     += c[ni][2];
                    acc_s[r1 * 32 + col + 1] += c[ni][3];
                }
                if (tig == 0) {
                    s_sv[r0] += c[4][0];
                    s_sv[r1] += c[4][2];
                }
            }
        }
        __syncthreads();                                  // sync #3
    }

    // partial state out
    int pbase = ((ch * Bk + b) * Hk + h) * Qk;
    for (int i = tid; i < Qk * Dk; i += 256) {
        int q = i >> 5, d = i & 31;
        g_pacc[(size_t)(pbase + q) * Dk + d] = acc_s[q * 32 + d];
    }
    for (int i = tid; i < Qk; i += 256)
        g_ps[pbase + i] = s_sv[i];
}

// Merge partial sums -> g_va_h (fp16).
__global__ void attn_merge()
{
    int i = blockIdx.x * 256 + threadIdx.x;
    if (i >= Bk * Hk * Qk * Dk) return;
    int d = i & 31;
    int qhb = i >> 5;
    int q = qhb % Qk;
    int hb = qhb / Qk;
    int h = hb % Hk, b = hb / Hk;

    float num = 0.f, den = 0.f;
#pragma unroll
    for (int ch = 0; ch < CHk; ch++) {
        int pb = ((ch * Bk + b) * Hk + h) * Qk + q;
        num += g_pacc[(size_t)pb * Dk + d];
        den += g_ps[pb];
    }
    g_va_h[((size_t)b * Qk + q) * Ck + h * Dk + d] = __float2half_rn(num / den);
}

// ---------------------------------------------------------------------------
extern "C" void kernel_launch(void* const* d_in, const int* in_sizes, int n_in,
                              void* d_out, int out_size)
{
    const float* vis  = (const float*)d_in[0];
    const float* lang = (const float*)d_in[1];
    const float* W_vk = (const float*)d_in[2];
    const float* b_vk = (const float*)d_in[3];
    const float* W_vv = (const float*)d_in[4];
    const float* b_vv = (const float*)d_in[5];
    const float* W_lk = (const float*)d_in[6];
    const float* b_lk = (const float*)d_in[7];
    const float* W_lv = (const float*)d_in[8];
    const float* b_lv = (const float*)d_in[9];
    const float* W0   = (const float*)d_in[10];
    const float* b0   = (const float*)d_in[11];
    const float* W1   = (const float*)d_in[12];
    const float* b1   = (const float*)d_in[13];

    float* out_p  = (float*)d_out;
    float* mask_p = out_p + (size_t)Bk * Qk * Ck;

    __half *p_vis_h, *p_lang_h, *p_kv_h, *p_lkv_h;
    __half *p_va_h, *p_la_h, *p_fm_h, *p_hid_h;
    __half *p_wT, *p_w0T, *p_w1T;
    float* p_bias4;
    cudaGetSymbolAddress((void**)&p_vis_h, g_vis_h);
    cudaGetSymbolAddress((void**)&p_lang_h, g_lang_h);
    cudaGetSymbolAddress((void**)&p_kv_h, g_kv_h);
    cudaGetSymbolAddress((void**)&p_lkv_h, g_lkv_h);
    cudaGetSymbolAddress((void**)&p_va_h, g_va_h);
    cudaGetSymbolAddress((void**)&p_la_h, g_la_h);
    cudaGetSymbolAddress((void**)&p_fm_h, g_fm_h);
    cudaGetSymbolAddress((void**)&p_hid_h, g_hid_h);
    cudaGetSymbolAddress((void**)&p_wT, g_wT_h);
    cudaGetSymbolAddress((void**)&p_w0T, g_w0T_h);
    cudaGetSymbolAddress((void**)&p_w1T, g_w1T_h);
    cudaGetSymbolAddress((void**)&p_bias4, g_bias4);

    cudaFuncSetAttribute(attn_tc, cudaFuncAttributeMaxDynamicSharedMemorySize, ATTN_SMEM);
    cudaFuncSetAttribute(mm_h<false, true, false, true>,
                         cudaFuncAttributeMaxDynamicSharedMemorySize, MMH_SMEM);
    cudaFuncSetAttribute(mm_h<false, false, true, true>,
                         cudaFuncAttributeMaxDynamicSharedMemorySize, MMH_SMEM);
    cudaFuncSetAttribute(mm_h<true, true, false, true>,
                         cudaFuncAttributeMaxDynamicSharedMemorySize, MMH_SMEM);
    cudaFuncSetAttribute(mm_h<false, true, true, false>,
                         cudaFuncAttributeMaxDynamicSharedMemorySize, MMH_SMEM);

    // 1: fused pre-pass
    prepass<<<NB_PRE, 256>>>(vis, lang, W_vk, W_vv, W_lk, W_lv, W0, W1,
                             b_vk, b_vv, b_lk, b_lv);

    // 2: vis K+V projections fused over z (BM=64)
    {
        dim3 g(Ck / 128, (Bk * HWk) / GEMM_BM, 2);
        mm_h<false, true, false, true><<<g, 256, MMH_SMEM>>>(
            p_vis_h, p_wT, p_bias4, nullptr, p_kv_h,
            Bk * HWk, Ck, Ck, 1.f,
            0, (long)Ck * Ck, (long)Bk * HWk * Ck, Ck);
    }
    // 3: lang K+V projections fused over z
    {
        dim3 g(Ck / 128, (Bk * Qk + 63) / 64, 2);
        mm_h<false, true, false, true><<<g, 256, MMH_SMEM>>>(
            p_lang_h, p_wT + 2 * Ck * Ck, p_bias4 + 2 * Ck, nullptr, p_lkv_h,
            Bk * Qk, Ck, Ck, 1.f,
            0, (long)Ck * Ck, (long)Bk * Qk * Ck, Ck);
    }

    // 4 (profiled): tensor-core attention
    {
        dim3 g(Bk * Hk, CHk);
        attn_tc<<<g, 256, ATTN_SMEM>>>();
        attn_merge<<<(Bk * Hk * Qk * Dk + 255) / 256, 256>>>();
    }

    // fm = (1/H) * Va @ La^T -> mask (fp32 output) + fm_h
    {
        dim3 g(HWk / 128, (Qk + 63) / 64, Bk);
        mm_h<false, false, true, true><<<g, 256, MMH_SMEM>>>(
            p_va_h, p_la_h, nullptr, mask_p, p_fm_h,
            Qk, HWk, Ck, 1.0f / Hk,
            (long)Qk * Ck, (long)HWk * Ck, (long)Qk * HWk, 0);
    }

    // hidden = relu(fm @ W0 + b0) -> fp16
    {
        dim3 g(HIDk / 128, (Bk * Qk + 63) / 64);
        mm_h<true, true, false, true><<<g, 256, MMH_SMEM>>>(
            p_fm_h, p_w0T, b0, nullptr, p_hid_h,
            Bk * Qk, HIDk, HWk, 1.f, 0, 0, 0, 0);
    }
    // out = hidden @ W1 + b1 -> fp32 (output)
    {
        dim3 g(Ck / 128, (Bk * Qk + 63) / 64);
        mm_h<false, true, true, false><<<g, 256, MMH_SMEM>>>(
            p_hid_h, p_w1T, b1, out_p, nullptr,
            Bk * Qk, Ck, HIDk, 1.f, 0, 0, 0, 0);
    }
}

// round 17
// speedup vs baseline: 1.0239x; 1.0239x over previous
#include <cuda_runtime.h>
#include <cuda_fp16.h>
#include <math.h>
#include <stdint.h>

// Problem constants
constexpr int Bk   = 16;
constexpr int HWk  = 4096;
constexpr int Qk   = 100;
constexpr int Ck   = 256;
constexpr int Hk   = 8;
constexpr int Dk   = 32;
constexpr int HIDk = 2048;
constexpr int CHk  = 8;
constexpr float SCALEk = 0.17677669529663687f;  // 32^-0.5

// Scratch (device globals: allocation-free rule)
__device__ float  g_pacc[CHk * Bk * Hk * Qk * Dk];
__device__ float  g_ps[CHk * Bk * Hk * Qk];
__device__ float  g_bias4[4 * Ck];
// fp16 pipeline buffers
__device__ __half g_vis_h[Bk * HWk * Ck];
__device__ __half g_lang_h[Bk * Qk * Ck];
__device__ __half g_kv_h[2 * Bk * HWk * Ck];   // [0]=vk, [1]=vv
__device__ __half g_lkv_h[2 * Bk * Qk * Ck];   // [0]=lk, [1]=lv
__device__ __half g_va_h[Bk * Qk * Ck];
__device__ __half g_la_h[Bk * HWk * Ck];
__device__ __half g_fm_h[Bk * Qk * HWk];
__device__ __half g_hid_h[Bk * Qk * HIDk];
__device__ __half g_wT_h[4 * Ck * Ck];
__device__ __half g_w0T_h[HIDk * HWk];
__device__ __half g_w1T_h[Ck * HIDk];

// ---------------------------------------------------------------------------
// PTX helpers (plain-sm_100-legal)
// ---------------------------------------------------------------------------
__device__ __forceinline__ uint32_t smem_u32(const void* p) {
    uint32_t a;
    asm("{ .reg .u64 t; cvta.to.shared.u64 t, %1; cvt.u32.u64 %0, t; }"
        : "=r"(a) : "l"(p));
    return a;
}
__device__ __forceinline__ void cpa16(uint32_t dst, const void* src, int srcsz) {
    asm volatile("cp.async.cg.shared.global [%0], [%1], 16, %2;"
                 :: "r"(dst), "l"(src), "r"(srcsz));
}
__device__ __forceinline__ void cpa_commit() {
    asm volatile("cp.async.commit_group;" ::: "memory");
}
__device__ __forceinline__ void cpa_wait1() {
    asm volatile("cp.async.wait_group 1;" ::: "memory");
}
__device__ __forceinline__ void cpa_wait0() {
    asm volatile("cp.async.wait_group 0;" ::: "memory");
}
__device__ __forceinline__ void ldsm4(uint32_t* r, uint32_t a) {
    asm volatile("ldmatrix.sync.aligned.m8n8.x4.shared.b16 {%0,%1,%2,%3}, [%4];"
                 : "=r"(r[0]), "=r"(r[1]), "=r"(r[2]), "=r"(r[3]) : "r"(a));
}
__device__ __forceinline__ void ldsm4t(uint32_t* r, uint32_t a) {
    asm volatile("ldmatrix.sync.aligned.m8n8.x4.trans.shared.b16 {%0,%1,%2,%3}, [%4];"
                 : "=r"(r[0]), "=r"(r[1]), "=r"(r[2]), "=r"(r[3]) : "r"(a));
}
__device__ __forceinline__ void mma16816(float* c, const uint32_t* a, const uint32_t* b) {
    asm volatile(
        "mma.sync.aligned.m16n8k16.row.col.f32.f16.f16.f32 "
        "{%0,%1,%2,%3},{%4,%5,%6,%7},{%8,%9},{%0,%1,%2,%3};"
        : "+f"(c[0]), "+f"(c[1]), "+f"(c[2]), "+f"(c[3])
        : "r"(a[0]), "r"(a[1]), "r"(a[2]), "r"(a[3]), "r"(b[0]), "r"(b[1]));
}

// ---------------------------------------------------------------------------
// Fused pre-pass (unchanged)
// ---------------------------------------------------------------------------
constexpr int NB_VIS  = Bk * HWk * Ck / 4 / 256;
constexpr int NB_LANG = Bk * Qk * Ck / 4 / 256;
constexpr int NB_T4   = (Ck / 32) * (Ck / 32) * 4;
constexpr int NB_W0   = (HIDk / 32) * (HWk / 32);
constexpr int NB_W1   = (Ck / 32) * (HIDk / 32);
constexpr int NB_BIAS = 1;
constexpr int NB_PRE  = NB_VIS + NB_LANG + NB_T4 + NB_W0 + NB_W1 + NB_BIAS;

__device__ __forceinline__ void tbody(const float* __restrict__ in,
                                      __half* __restrict__ out,
                                      int R, int C, int bx, int by,
                                      int tx, int ty)
{
    __shared__ float t[32][33];
    int r0 = by * 32, c0 = bx * 32;
#pragma unroll
    for (int i = 0; i < 4; i++)
        t[ty + 8 * i][tx] = in[(size_t)(r0 + ty + 8 * i) * C + c0 + tx];
    __syncthreads();
#pragma unroll
    for (int i = 0; i < 4; i++)
        out[(size_t)(c0 + ty + 8 * i) * R + r0 + tx] =
            __float2half_rn(t[tx][ty + 8 * i]);
}

__global__ __launch_bounds__(256) void prepass(
    const float* __restrict__ vis, const float* __restrict__ lang,
    const float* __restrict__ Wvk, const float* __restrict__ Wvv,
    const float* __restrict__ Wlk, const float* __restrict__ Wlv,
    const float* __restrict__ W0, const float* __restrict__ W1,
    const float* __restrict__ bvk, const float* __restrict__ bvv,
    const float* __restrict__ blk, const float* __restrict__ blv)
{
    int bid = blockIdx.x;
    int tid = threadIdx.x;
    int tx = tid & 31, ty = tid >> 5;

    if (bid < NB_VIS) {
        int i = (bid * 256 + tid) * 4;
        float4 v = *(const float4*)(vis + i);
        *(__half2*)(g_vis_h + i)     = __floats2half2_rn(v.x, v.y);
        *(__half2*)(g_vis_h + i + 2) = __floats2half2_rn(v.z, v.w);
        return;
    }
    bid -= NB_VIS;
    if (bid < NB_LANG) {
        int i = (bid * 256 + tid) * 4;
        float4 v = *(const float4*)(lang + i);
        *(__half2*)(g_lang_h + i)     = __floats2half2_rn(v.x, v.y);
        *(__half2*)(g_lang_h + i + 2) = __floats2half2_rn(v.z, v.w);
        return;
    }
    bid -= NB_LANG;
    if (bid < NB_T4) {
        int z = bid / 64, rem = bid % 64;
        const float* in = (z == 0) ? Wvk : (z == 1) ? Wvv : (z == 2) ? Wlk : Wlv;
        tbody(in, g_wT_h + (size_t)z * Ck * Ck, Ck, Ck, rem % 8, rem / 8, tx, ty);
        return;
    }
    bid -= NB_T4;
    if (bid < NB_W0) {
        tbody(W0, g_w0T_h, HWk, HIDk, bid % (HIDk / 32), bid / (HIDk / 32), tx, ty);
        return;
    }
    bid -= NB_W0;
    if (bid < NB_W1) {
        tbody(W1, g_w1T_h, HIDk, Ck, bid % (Ck / 32), bid / (Ck / 32), tx, ty);
        return;
    }
    {
        int i = tid * 4;
        int j = i >> 8;
        const float* src = (j == 0) ? bvk : (j == 1) ? bvv : (j == 2) ? blk : blv;
        *(float4*)(g_bias4 + i) = *(const float4*)(src + (i & 255));
    }
}

// ---------------------------------------------------------------------------
// fp16 tensor-core GEMM, templated BM. BM=64 uses register fragment
// double-buffering (fits reg cap at MI=2); BM=128 keeps single-buffer loop.
// ---------------------------------------------------------------------------
constexpr int STAGES = 3;
constexpr int MMH_SMEM_OF(int BM) { return STAGES * (BM * 128 + 16384); }

template <int BM, bool RELU, bool HASBIAS, bool OUT32, bool OUTH>
__global__ __launch_bounds__(256, 2) void mm_h(
    const __half* __restrict__ Ag, const __half* __restrict__ Bg,
    const float* __restrict__ bias, float* __restrict__ Cf, __half* __restrict__ Ch,
    int M, int N, int K, float alpha, long sA, long sB, long sC, long sBias)
{
    constexpr int MI = BM / 32;
    constexpr int ASTG = BM * 128;
    constexpr int STRIDE = ASTG + 16384;

    extern __shared__ char smh[];
    const __half* A = Ag + (size_t)blockIdx.z * sA;
    const __half* B = Bg + (size_t)blockIdx.z * sB;
    const float* bi = HASBIAS ? bias + (size_t)blockIdx.z * sBias : nullptr;

    const int tid = threadIdx.x, lane = tid & 31, warp = tid >> 5;
    const int warp_m = warp >> 2, warp_n = warp & 3;
    const int bm = blockIdx.y * BM, bn = blockIdx.x * 128;
    const uint32_t sbase = smem_u32(smh);
    const int NS = K / 64;

    auto issue = [&](int s) {
        uint32_t ab = sbase + (s % STAGES) * STRIDE;
        uint32_t bb = ab + ASTG;
        int k0 = s * 64;
#pragma unroll
        for (int i = 0; i < BM / 32; i++) {
            int id = tid + 256 * i;
            int r = id >> 3, c = id & 7;
            uint32_t off = r * 128 + ((c ^ (r & 7)) << 4);
            cpa16(ab + off, A + (size_t)(bm + r) * K + k0 + c * 8,
                  (bm + r) < M ? 16 : 0);
        }
#pragma unroll
        for (int i = 0; i < 4; i++) {
            int id = tid + 256 * i;
            int r = id >> 3, c = id & 7;
            uint32_t off = r * 128 + ((c ^ (r & 7)) << 4);
            cpa16(bb + off, B + (size_t)(bn + r) * K + k0 + c * 8, 16);
        }
    };

    float acc[MI][4][4] = {};

    issue(0); cpa_commit();
    if (NS > 1) issue(1);
    cpa_commit();

    for (int s = 0; s < NS; s++) {
        cpa_wait1();
        __syncthreads();
        uint32_t ab = sbase + (s % STAGES) * STRIDE;
        uint32_t bb = ab + ASTG;

        if constexpr (MI == 2) {
            // register fragment double-buffering
            uint32_t af[2][MI][4], bf[2][4][2];
            auto ldA = [&](int ks, uint32_t (*A_)[4]) {
#pragma unroll
                for (int mi = 0; mi < MI; mi++) {
                    int row = warp_m * (BM / 2) + mi * 16 + (lane & 15);
                    int kc = ks * 2 + ((lane >> 4) & 1);
                    ldsm4(A_[mi], ab + row * 128 + ((kc ^ (row & 7)) << 4));
                }
            };
            auto ldB = [&](int ks, uint32_t (*B_)[2]) {
#pragma unroll
                for (int bj = 0; bj < 2; bj++) {
                    int row = warp_n * 32 + bj * 16 + (lane & 7) + ((lane >> 4) << 3);
                    int kc = ks * 2 + ((lane >> 3) & 1);
                    uint32_t t[4];
                    ldsm4(t, bb + row * 128 + ((kc ^ (row & 7)) << 4));
                    B_[bj * 2][0] = t[0]; B_[bj * 2][1] = t[1];
                    B_[bj * 2 + 1][0] = t[2]; B_[bj * 2 + 1][1] = t[3];
                }
            };
            ldA(0, af[0]); ldB(0, bf[0]);
#pragma unroll
            for (int ks = 0; ks < 4; ks++) {
                if (ks < 3) { ldA(ks + 1, af[(ks + 1) & 1]); ldB(ks + 1, bf[(ks + 1) & 1]); }
#pragma unroll
                for (int mi = 0; mi < MI; mi++)
#pragma unroll
                    for (int ni = 0; ni < 4; ni++)
                        mma16816(acc[mi][ni], af[ks & 1][mi], bf[ks & 1][ni]);
            }
        } else {
            // single-buffered (register pressure at MI=4)
#pragma unroll
            for (int ks = 0; ks < 4; ks++) {
                uint32_t af[MI][4], bf[4][2];
#pragma unroll
                for (int mi = 0; mi < MI; mi++) {
                    int row = warp_m * (BM / 2) + mi * 16 + (lane & 15);
                    int kc = ks * 2 + ((lane >> 4) & 1);
                    ldsm4(af[mi], ab + row * 128 + ((kc ^ (row & 7)) << 4));
                }
#pragma unroll
                for (int bj = 0; bj < 2; bj++) {
                    int row = warp_n * 32 + bj * 16 + (lane & 7) + ((lane >> 4) << 3);
                    int kc = ks * 2 + ((lane >> 3) & 1);
                    uint32_t t[4];
                    ldsm4(t, bb + row * 128 + ((kc ^ (row & 7)) << 4));
                    bf[bj * 2][0] = t[0]; bf[bj * 2][1] = t[1];
                    bf[bj * 2 + 1][0] = t[2]; bf[bj * 2 + 1][1] = t[3];
                }
#pragma unroll
                for (int mi = 0; mi < MI; mi++)
#pragma unroll
                    for (int ni = 0; ni < 4; ni++)
                        mma16816(acc[mi][ni], af[mi], bf[ni]);
            }
        }
        if (s + STAGES - 1 < NS) issue(s + STAGES - 1);
        cpa_commit();
    }

    const int rr = lane >> 2, cc2 = (lane & 3) * 2;
#pragma unroll
    for (int mi = 0; mi < MI; mi++) {
        int row0 = bm + warp_m * (BM / 2) + mi * 16 + rr;
#pragma unroll
        for (int ni = 0; ni < 4; ni++) {
            int col = bn + warp_n * 32 + ni * 8 + cc2;
            float b0 = HASBIAS ? bi[col] : 0.f;
            float b1 = HASBIAS ? bi[col + 1] : 0.f;
            float v0 = alpha * acc[mi][ni][0] + b0;
            float v1 = alpha * acc[mi][ni][1] + b1;
            float v2 = alpha * acc[mi][ni][2] + b0;
            float v3 = alpha * acc[mi][ni][3] + b1;
            if (RELU) {
                v0 = fmaxf(v0, 0.f); v1 = fmaxf(v1, 0.f);
                v2 = fmaxf(v2, 0.f); v3 = fmaxf(v3, 0.f);
            }
            if (row0 < M) {
                size_t o = (size_t)blockIdx.z * sC + (size_t)row0 * N + col;
                if (OUT32) *(float2*)(Cf + o) = make_float2(v0, v1);
                if (OUTH)  *(__half2*)(Ch + o) = __floats2half2_rn(v0, v1);
            }
            if (row0 + 8 < M) {
                size_t o = (size_t)blockIdx.z * sC + (size_t)(row0 + 8) * N + col;
                if (OUT32) *(float2*)(Cf + o) = make_float2(v2, v3);
                if (OUTH)  *(__half2*)(Ch + o) = __floats2half2_rn(v2, v3);
            }
        }
    }
}

// ---------------------------------------------------------------------------
// Max-free tensor-core attention (unchanged, 2 CTAs/SM)
// ---------------------------------------------------------------------------
constexpr int OFF_LK  = 0;
constexpr int OFF_VK0 = OFF_LK + 112 * 128;
constexpr int OFF_LVT = OFF_VK0 + 32768;
constexpr int OFF_VVT = OFF_LVT + 48 * 256;
constexpr int OFF_PQ  = OFF_VVT + 48 * 256;
constexpr int OFF_ACC = OFF_PQ + 112 * 256;
constexpr int OFF_SS  = OFF_ACC + 112 * 32 * 4;
constexpr int ATTN_SMEM = OFF_SS + 448;

__global__ __launch_bounds__(256, 2) void attn_tc()
{
    int bh = blockIdx.x, ch = blockIdx.y;
    int b = bh / Hk, h = bh % Hk;
    int tid = threadIdx.x, lane = tid & 31, warp = tid >> 5;
    const int rrL = lane >> 2, tig = lane & 3, ccL = tig * 2;

    const __half* vkg = g_kv_h;
    const __half* vvg = g_kv_h + (size_t)Bk * HWk * Ck;
    const __half* lkg = g_lkv_h;
    const __half* lvg = g_lkv_h + (size_t)Bk * Qk * Ck;

    extern __shared__ char smn[];
    const uint32_t sU = smem_u32(smn);
    float* acc_s = (float*)(smn + OFF_ACC);
    float* s_sv  = (float*)(smn + OFF_SS);

    const int TILES = HWk / 128 / CHk;
    const int t0 = ch * TILES;

    auto issue_vk = [&](int kt, int buf) {
#pragma unroll
        for (int i = 0; i < 2; i++) {
            int id = tid + 256 * i;
            int r = id >> 2, kc = id & 3;
            cpa16(sU + OFF_VK0 + buf * 16384 + r * 128 + ((kc ^ (r & 7)) << 4),
                  vkg + ((size_t)b * HWk + kt * 128 + r) * Ck + h * Dk + kc * 8, 16);
        }
    };
    auto ldg_vv = [&](int kt, uint4* regs) {
#pragma unroll
        for (int i = 0; i < 2; i++) {
            int id = tid + 256 * i;
            int r = id >> 2, kc = id & 3;
            regs[i] = *(const uint4*)(vvg + ((size_t)b * HWk + kt * 128 + r) * Ck
                                      + h * Dk + kc * 8);
        }
    };

    issue_vk(t0, 0); cpa_commit();
    uint4 vvr[2];
    ldg_vv(t0, vvr);

    // ---- one-time setup ----
    for (int i = tid; i < 112 * 4; i += 256) {
        int r = i >> 2, kc = i & 3;
        uint4 v = make_uint4(0, 0, 0, 0);
        if (r < Qk)
            v = *(const uint4*)(lkg + ((size_t)b * Qk + r) * Ck + h * Dk + kc * 8);
        *(uint4*)(smn + OFF_LK + r * 128 + ((kc ^ (r & 7)) << 4)) = v;
    }
    for (int i = tid; i < 32 * 112; i += 256) {
        int q = i >> 5, d = i & 31;
        __half v = __ushort_as_half(0);
        if (q < Qk) v = lvg[((size_t)b * Qk + q) * Ck + h * Dk + d];
        *(__half*)(smn + OFF_LVT + d * 256 + (((q >> 3) ^ (d & 7)) << 4) + (q & 7) * 2) = v;
    }
    for (int i = tid; i < 16 * 128; i += 256) {
        int d = 32 + (i >> 7), c = i & 127;
        __half onesL = (d == 32 && c < Qk) ? __float2half_rn(1.f) : __ushort_as_half(0);
        __half onesV = (d == 32) ? __float2half_rn(1.f) : __ushort_as_half(0);
        uint32_t sw = (((c >> 3) ^ (d & 7)) << 4) + (c & 7) * 2;
        *(__half*)(smn + OFF_LVT + d * 256 + sw) = onesL;
        *(__half*)(smn + OFF_VVT + d * 256 + sw) = onesV;
    }
    for (int i = tid; i < 112 * 32; i += 256) acc_s[i] = 0.f;
    for (int i = tid; i < 112; i += 256) s_sv[i] = 0.f;

    for (int it = 0; it < TILES; it++) {
        const int kt = t0 + it;
        const int k0 = kt * 128;
        const int vb = it & 1;

#pragma unroll
        for (int i = 0; i < 2; i++) {
            int id = tid + 256 * i;
            int r = id >> 2, kc = id & 3;
            uint32_t w[4] = { vvr[i].x, vvr[i].y, vvr[i].z, vvr[i].w };
#pragma unroll
            for (int j = 0; j < 4; j++) {
                __half2 h2 = *reinterpret_cast<__half2*>(&w[j]);
                int d0 = kc * 8 + j * 2, d1 = d0 + 1;
                *(__half*)(smn + OFF_VVT + d0 * 256 +
                           (((r >> 3) ^ (d0 & 7)) << 4) + (r & 7) * 2) = h2.x;
                *(__half*)(smn + OFF_VVT + d1 * 256 +
                           (((r >> 3) ^ (d1 & 7)) << 4) + (r & 7) * 2) = h2.y;
            }
        }

        if (it + 1 < TILES) { issue_vk(kt + 1, vb ^ 1); cpa_commit(); cpa_wait1(); }
        else cpa_wait0();
        __syncthreads();                                  // sync #1

        // ---- S = lk @ vk^T in two mi-halves; exp in registers -> Pq ----
        {
            int n0 = warp * 16;
#pragma unroll
            for (int hf = 0; hf < 2; hf++) {
                const int mBase = hf * 4;
                const int mCnt = hf ? 3 : 4;
                float c[4][2][4] = {};
#pragma unroll
                for (int ks = 0; ks < 2; ks++) {
                    uint32_t bfr[4];
                    {
                        int row = n0 + (lane & 7) + ((lane >> 4) << 3);
                        int kc = ks * 2 + ((lane >> 3) & 1);
                        ldsm4(bfr, sU + OFF_VK0 + vb * 16384 + row * 128 +
                                   ((kc ^ (row & 7)) << 4));
                    }
#pragma unroll
                    for (int mi = 0; mi < 4; mi++) {
                        if (mi >= mCnt) break;
                        uint32_t af[4];
                        int row = (mBase + mi) * 16 + (lane & 15);
                        int kc = ks * 2 + (lane >> 4);
                        ldsm4(af, sU + OFF_LK + row * 128 + ((kc ^ (row & 7)) << 4));
                        uint32_t b0[2] = {bfr[0], bfr[1]}, b1[2] = {bfr[2], bfr[3]};
                        mma16816(c[mi][0], af, b0);
                        mma16816(c[mi][1], af, b1);
                    }
                }
#pragma unroll
                for (int mi = 0; mi < 4; mi++) {
                    if (mi >= mCnt) break;
                    int q0 = (mBase + mi) * 16 + rrL;
#pragma unroll
                    for (int ni = 0; ni < 2; ni++) {
                        int kc0 = n0 + ni * 8 + ccL;
                        float e0 = __expf(c[mi][ni][0] * SCALEk);
                        float e1 = __expf(c[mi][ni][1] * SCALEk);
                        float e2 = __expf(c[mi][ni][2] * SCALEk);
                        float e3 = __expf(c[mi][ni][3] * SCALEk);
                        *(__half2*)(smn + OFF_PQ + q0 * 256 +
                                    (((kc0 >> 3) ^ (q0 & 7)) << 4) + (kc0 & 7) * 2) =
                            __floats2half2_rn(e0, e1);
                        *(__half2*)(smn + OFF_PQ + (q0 + 8) * 256 +
                                    (((kc0 >> 3) ^ ((q0 + 8) & 7)) << 4) + (kc0 & 7) * 2) =
                            __floats2half2_rn(e2, e3);
                    }
                }
            }
        }
        if (it + 1 < TILES) ldg_vv(kt + 1, vvr);
        __syncthreads();                                  // sync #2

        // ---- concurrent: warps 0-3 la MMA (trans A from Pq), warps 4-7 pv MMA ----
        if (warp < 4) {
#pragma unroll
            for (int c2 = 0; c2 < 2; c2++) {
                int m0 = warp * 16 + c2 * 64;
                float c[5][4] = {};
#pragma unroll
                for (int ks = 0; ks < 7; ks++) {
                    uint32_t af[4];
                    {
                        int q = ks * 16 + ((lane >> 4) << 3) + (lane & 7);
                        int mcol = m0 + (((lane >> 3) & 1) << 3);
                        ldsm4t(af, sU + OFF_PQ + q * 256 +
                                   ((((mcol >> 3) ^ (q & 7)) << 4)));
                    }
#pragma unroll
                    for (int bj = 0; bj < 3; bj++) {
                        int row = bj * 16 + (lane & 7) + ((lane >> 4) << 3);
                        int kc = ks * 2 + ((lane >> 3) & 1);
                        uint32_t t[4];
                        ldsm4(t, sU + OFF_LVT + row * 256 + ((kc ^ (row & 7)) << 4));
                        uint32_t b0[2] = {t[0], t[1]}, b1[2] = {t[2], t[3]};
                        mma16816(c[bj * 2], af, b0);
                        if (bj < 2) mma16816(c[bj * 2 + 1], af, b1);
                    }
                }
                int kr0 = m0 + rrL, kr1 = kr0 + 8;
                float cs0 = __shfl_sync(0xFFFFFFFFu, c[4][0], (lane >> 2) << 2);
                float cs1 = __shfl_sync(0xFFFFFFFFu, c[4][2], (lane >> 2) << 2);
                float inv0 = 1.f / cs0, inv1 = 1.f / cs1;
#pragma unroll
                for (int ni = 0; ni < 4; ni++) {
                    int d0 = ni * 8 + ccL;
                    size_t o0 = ((size_t)b * HWk + k0 + kr0) * Ck + h * Dk + d0;
                    size_t o1 = ((size_t)b * HWk + k0 + kr1) * Ck + h * Dk + d0;
                    *(__half2*)(g_la_h + o0) =
                        __floats2half2_rn(c[ni][0] * inv0, c[ni][1] * inv0);
                    *(__half2*)(g_la_h + o1) =
                        __floats2half2_rn(c[ni][2] * inv1, c[ni][3] * inv1);
                }
            }
        } else {
            int wq = warp - 4;
#pragma unroll
            for (int c2 = 0; c2 < 2; c2++) {
                int chunk = wq + c2 * 4;
                if (chunk >= 7) break;
                int m0 = chunk * 16;
                float c[5][4] = {};
#pragma unroll
                for (int ks = 0; ks < 8; ks++) {
                    uint32_t af[4];
                    {
                        int row = m0 + (lane & 15);
                        int kc = ks * 2 + (lane >> 4);
                        ldsm4(af, sU + OFF_PQ + row * 256 + ((kc ^ (row & 7)) << 4));
                    }
#pragma unroll
                    for (int bj = 0; bj < 3; bj++) {
                        int row = bj * 16 + (lane & 7) + ((lane >> 4) << 3);
                        int kc = ks * 2 + ((lane >> 3) & 1);
                        uint32_t t[4];
                        ldsm4(t, sU + OFF_VVT + row * 256 + ((kc ^ (row & 7)) << 4));
                        uint32_t b0[2] = {t[0], t[1]}, b1[2] = {t[2], t[3]};
                        mma16816(c[bj * 2], af, b0);
                        if (bj < 2) mma16816(c[bj * 2 + 1], af, b1);
                    }
                }
                int r0 = m0 + rrL, r1 = r0 + 8;
#pragma unroll
                for (int ni = 0; ni < 4; ni++) {
                    int col = ni * 8 + ccL;
                    acc_s[r0 * 32 + col]     += c[ni][0];
                    acc_s[r0 * 32 + col + 1] += c[ni][1];
                    acc_s[r1 * 32 + col]     += c[ni][2];
                    acc_s[r1 * 32 + col + 1] += c[ni][3];
                }
                if (tig == 0) {
                    s_sv[r0] += c[4][0];
                    s_sv[r1] += c[4][2];
                }
            }
        }
        __syncthreads();                                  // sync #3
    }

    // partial state out
    int pbase = ((ch * Bk + b) * Hk + h) * Qk;
    for (int i = tid; i < Qk * Dk; i += 256) {
        int q = i >> 5, d = i & 31;
        g_pacc[(size_t)(pbase + q) * Dk + d] = acc_s[q * 32 + d];
    }
    for (int i = tid; i < Qk; i += 256)
        g_ps[pbase + i] = s_sv[i];
}

// Merge partial sums -> g_va_h (fp16).
__global__ void attn_merge()
{
    int i = blockIdx.x * 256 + threadIdx.x;
    if (i >= Bk * Hk * Qk * Dk) return;
    int d = i & 31;
    int qhb = i >> 5;
    int q = qhb % Qk;
    int hb = qhb / Qk;
    int h = hb % Hk, b = hb / Hk;

    float num = 0.f, den = 0.f;
#pragma unroll
    for (int ch = 0; ch < CHk; ch++) {
        int pb = ((ch * Bk + b) * Hk + h) * Qk + q;
        num += g_pacc[(size_t)pb * Dk + d];
        den += g_ps[pb];
    }
    g_va_h[((size_t)b * Qk + q) * Ck + h * Dk + d] = __float2half_rn(num / den);
}

// ---------------------------------------------------------------------------
extern "C" void kernel_launch(void* const* d_in, const int* in_sizes, int n_in,
                              void* d_out, int out_size)
{
    const float* vis  = (const float*)d_in[0];
    const float* lang = (const float*)d_in[1];
    const float* W_vk = (const float*)d_in[2];
    const float* b_vk = (const float*)d_in[3];
    const float* W_vv = (const float*)d_in[4];
    const float* b_vv = (const float*)d_in[5];
    const float* W_lk = (const float*)d_in[6];
    const float* b_lk = (const float*)d_in[7];
    const float* W_lv = (const float*)d_in[8];
    const float* b_lv = (const float*)d_in[9];
    const float* W0   = (const float*)d_in[10];
    const float* b0   = (const float*)d_in[11];
    const float* W1   = (const float*)d_in[12];
    const float* b1   = (const float*)d_in[13];

    float* out_p  = (float*)d_out;
    float* mask_p = out_p + (size_t)Bk * Qk * Ck;

    __half *p_vis_h, *p_lang_h, *p_kv_h, *p_lkv_h;
    __half *p_va_h, *p_la_h, *p_fm_h, *p_hid_h;
    __half *p_wT, *p_w0T, *p_w1T;
    float* p_bias4;
    cudaGetSymbolAddress((void**)&p_vis_h, g_vis_h);
    cudaGetSymbolAddress((void**)&p_lang_h, g_lang_h);
    cudaGetSymbolAddress((void**)&p_kv_h, g_kv_h);
    cudaGetSymbolAddress((void**)&p_lkv_h, g_lkv_h);
    cudaGetSymbolAddress((void**)&p_va_h, g_va_h);
    cudaGetSymbolAddress((void**)&p_la_h, g_la_h);
    cudaGetSymbolAddress((void**)&p_fm_h, g_fm_h);
    cudaGetSymbolAddress((void**)&p_hid_h, g_hid_h);
    cudaGetSymbolAddress((void**)&p_wT, g_wT_h);
    cudaGetSymbolAddress((void**)&p_w0T, g_w0T_h);
    cudaGetSymbolAddress((void**)&p_w1T, g_w1T_h);
    cudaGetSymbolAddress((void**)&p_bias4, g_bias4);

    constexpr int SM128 = MMH_SMEM_OF(128);
    constexpr int SM64  = MMH_SMEM_OF(64);
    cudaFuncSetAttribute(attn_tc, cudaFuncAttributeMaxDynamicSharedMemorySize, ATTN_SMEM);
    cudaFuncSetAttribute(mm_h<128, false, true, false, true>,
                         cudaFuncAttributeMaxDynamicSharedMemorySize, SM128);
    cudaFuncSetAttribute(mm_h<64, false, true, false, true>,
                         cudaFuncAttributeMaxDynamicSharedMemorySize, SM64);
    cudaFuncSetAttribute(mm_h<64, false, false, true, true>,
                         cudaFuncAttributeMaxDynamicSharedMemorySize, SM64);
    cudaFuncSetAttribute(mm_h<64, true, true, false, true>,
                         cudaFuncAttributeMaxDynamicSharedMemorySize, SM64);
    cudaFuncSetAttribute(mm_h<64, false, true, true, false>,
                         cudaFuncAttributeMaxDynamicSharedMemorySize, SM64);

    // 1: fused pre-pass
    prepass<<<NB_PRE, 256>>>(vis, lang, W_vk, W_vv, W_lk, W_lv, W0, W1,
                             b_vk, b_vv, b_lk, b_lv);

    // 2: vis K+V projections fused over z (BM=128)
    {
        dim3 g(Ck / 128, (Bk * HWk) / 128, 2);
        mm_h<128, false, true, false, true><<<g, 256, SM128>>>(
            p_vis_h, p_wT, p_bias4, nullptr, p_kv_h,
            Bk * HWk, Ck, Ck, 1.f,
            0, (long)Ck * Ck, (long)Bk * HWk * Ck, Ck);
    }
    // 3: lang K+V projections fused over z (BM=64)
    {
        dim3 g(Ck / 128, (Bk * Qk + 63) / 64, 2);
        mm_h<64, false, true, false, true><<<g, 256, SM64>>>(
            p_lang_h, p_wT + 2 * Ck * Ck, p_bias4 + 2 * Ck, nullptr, p_lkv_h,
            Bk * Qk, Ck, Ck, 1.f,
            0, (long)Ck * Ck, (long)Bk * Qk * Ck, Ck);
    }

    // 4 (profiled): tensor-core attention
    {
        dim3 g(Bk * Hk, CHk);
        attn_tc<<<g, 256, ATTN_SMEM>>>();
        attn_merge<<<(Bk * Hk * Qk * Dk + 255) / 256, 256>>>();
    }

    // fm = (1/H) * Va @ La^T -> mask (fp32 output) + fm_h  (BM=64)
    {
        dim3 g(HWk / 128, (Qk + 63) / 64, Bk);
        mm_h<64, false, false, true, true><<<g, 256, SM64>>>(
            p_va_h, p_la_h, nullptr, mask_p, p_fm_h,
            Qk, HWk, Ck, 1.0f / Hk,
            (long)Qk * Ck, (long)HWk * Ck, (long)Qk * HWk, 0);
    }

    // hidden = relu(fm @ W0 + b0) -> fp16  (BM=64)
    {
        dim3 g(HIDk / 128, (Bk * Qk + 63) / 64);
        mm_h<64, true, true, false, true><<<g, 256, SM64>>>(
            p_fm_h, p_w0T, b0, nullptr, p_hid_h,
            Bk * Qk, HIDk, HWk, 1.f, 0, 0, 0, 0);
    }
    // out = hidden @ W1 + b1 -> fp32 (output)  (BM=64)
    {
        dim3 g(Ck / 128, (Bk * Qk + 63) / 64);
        mm_h<64, false, true, true, false><<<g, 256, SM64>>>(
            p_hid_h, p_w1T, b1, out_p, nullptr,
            Bk * Qk, Ck, HIDk, 1.f, 0, 0, 0, 0);
    }
}